// round 1
// baseline (speedup 1.0000x reference)
#include <cuda_runtime.h>
#include <stdint.h>

#define BATCH   64
#define NA      3234
#define NC      91
#define CM1     90
#define CAP     512
#define KMAX    200
#define POOLCAP 16384

typedef unsigned long long u64;
typedef unsigned int u32;

// -------- scratch (static __device__ — no allocations allowed) --------
__device__ float4 g_boxes[BATCH * NA];                       // decoded boxes
__device__ u64    g_cand[(size_t)BATCH * CM1 * CAP];         // per (b,c) candidates > thresh
__device__ int    g_candCnt[BATCH * CM1];
__device__ u64    g_pool[(size_t)BATCH * POOLCAP];           // per image kept detections
__device__ int    g_poolCnt[BATCH];

// ~1-ulp exp, FMA-only (immune to fast-math substitution). Valid for |x| < ~80.
__device__ __forceinline__ float exp_acc(float x) {
    float k = rintf(x * 1.44269504088896340736f);
    float r = fmaf(k, -0.693359375f, x);
    r = fmaf(k, 2.12194440054690582762e-4f, r);
    float p = 1.98412698412698413e-4f;            // 1/5040
    p = fmaf(p, r, 1.38888888888888889e-3f);      // 1/720
    p = fmaf(p, r, 8.33333333333333333e-3f);      // 1/120
    p = fmaf(p, r, 4.16666666666666667e-2f);      // 1/24
    p = fmaf(p, r, 1.66666666666666667e-1f);      // 1/6
    p = fmaf(p, r, 0.5f);
    p = fmaf(p, r, 1.0f);
    p = fmaf(p, r, 1.0f);
    int ki = (int)k;
    ki = max(-126, min(126, ki));
    return p * __int_as_float((ki + 127) << 23);
}

// -------- kernel 0: zero counters --------
__global__ void k_zero() {
    int i = blockIdx.x * blockDim.x + threadIdx.x;
    if (i < BATCH * CM1) g_candCnt[i] = 0;
    if (i < BATCH) g_poolCnt[i] = 0;
}

// -------- kernel 1a: decode boxes --------
__global__ void k_decode(const float* __restrict__ box_reg,
                         const float* __restrict__ priors) {
    int i = blockIdx.x * blockDim.x + threadIdx.x;
    if (i >= BATCH * NA) return;
    int a = i % NA;
    float4 loc = ((const float4*)box_reg)[i];
    float4 pr  = ((const float4*)priors)[a];
    float pw = pr.z - pr.x, ph = pr.w - pr.y;
    float cx = pr.x + 0.5f * pw, cy = pr.y + 0.5f * ph;
    float x = loc.x * 0.1f * pw + cx;
    float y = loc.y * 0.1f * ph + cy;
    float w = exp_acc(loc.z * 0.2f) * pw;
    float h = exp_acc(loc.w * 0.2f) * ph;
    g_boxes[i] = make_float4(x - w * 0.5f, y - h * 0.5f, x + w * 0.5f, y + h * 0.5f);
}

// -------- kernel 1b: fused softmax + threshold filter (warp per anchor) --------
__device__ __forceinline__ void push_cand(float e, int c, int b, int a, float s, float pre) {
    if (c >= 1 && c < NC && e > pre) {
        float p = __fdiv_rn(e, s);                 // exact softmax value
        if (p > 0.05f) {
            int li = b * CM1 + (c - 1);
            int pos = atomicAdd(&g_candCnt[li], 1);
            if (pos < CAP)
                g_cand[(size_t)li * CAP + pos] =
                    ((u64)__float_as_uint(p) << 32) | (u32)(~(u32)a);
        }
    }
}

__global__ void __launch_bounds__(256) k_cand(const float* __restrict__ logits) {
    int gw = (blockIdx.x * 256 + threadIdx.x) >> 5;
    int lane = threadIdx.x & 31;
    if (gw >= BATCH * NA) return;
    int b = gw / NA;
    int a = gw - b * NA;
    const float* L = logits + (size_t)gw * NC;
    float l0 = L[lane];
    float l1 = L[lane + 32];
    float l2 = (lane < NC - 64) ? L[lane + 64] : -1e30f;
    float mx = fmaxf(l0, fmaxf(l1, l2));
#pragma unroll
    for (int o = 16; o; o >>= 1) mx = fmaxf(mx, __shfl_xor_sync(0xffffffffu, mx, o));
    float e0 = exp_acc(l0 - mx);
    float e1 = exp_acc(l1 - mx);
    float e2 = (lane < NC - 64) ? exp_acc(l2 - mx) : 0.0f;
    float s = e0 + e1 + e2;
#pragma unroll
    for (int o = 16; o; o >>= 1) s += __shfl_xor_sync(0xffffffffu, s, o);
    float pre = 0.0495f * s;   // conservative prefilter; exact test inside push_cand
    push_cand(e0, lane,      b, a, s, pre);
    push_cand(e1, lane + 32, b, a, s, pre);
    push_cand(e2, lane + 64, b, a, s, pre);
}

// -------- kernel 2: per (b,c) sort + greedy NMS --------
__global__ void __launch_bounds__(128) k_nms() {
    __shared__ u64 keys[CAP];
    __shared__ float bx0[KMAX], by0[KMAX], bx1[KMAX], by1[KMAX], ar[KMAX];
    __shared__ u32 mask[KMAX * 8];
    __shared__ int kl[KMAX];
    __shared__ int sh_nk, sh_base;

    int c = blockIdx.x, b = blockIdx.y;
    int li = b * CM1 + c;
    int m = g_candCnt[li];
    if (m > CAP) m = CAP;
    if (m == 0) return;
    int tid = threadIdx.x;

    int n = 1; while (n < m) n <<= 1;       // pow2 sort size, <= 512
    for (int i = tid; i < n; i += 128)
        keys[i] = (i < m) ? g_cand[(size_t)li * CAP + i] : 0ULL;
    __syncthreads();

    // bitonic sort descending (keys: score desc, anchor asc — matches lax.top_k)
    for (int k = 2; k <= n; k <<= 1)
        for (int j = k >> 1; j > 0; j >>= 1) {
            for (int i = tid; i < n; i += 128) {
                int x = i ^ j;
                if (x > i) {
                    u64 A = keys[i], Bv = keys[x];
                    bool up = (i & k) == 0;
                    if (up ? (A < Bv) : (A > Bv)) { keys[i] = Bv; keys[x] = A; }
                }
            }
            __syncthreads();
        }

    int K = m < KMAX ? m : KMAX;
    for (int r = tid; r < K; r += 128) {
        int a = (int)(~(u32)keys[r]);
        float4 bb = g_boxes[b * NA + a];
        bx0[r] = bb.x; by0[r] = bb.y; bx1[r] = bb.z; by1[r] = bb.w;
        ar[r] = fmaxf(bb.z - bb.x, 0.f) * fmaxf(bb.w - bb.y, 0.f);
    }
    __syncthreads();

    // IoU suppression bitmatrix (j > i)
    int W = (K + 31) >> 5;
    for (int w = tid; w < K * W; w += 128) {
        int i = w / W, seg = w - i * W;
        u32 bits = 0;
        float xi0 = bx0[i], yi0 = by0[i], xi1 = bx1[i], yi1 = by1[i], ai = ar[i];
        int j0 = seg << 5;
        int je = min(j0 + 32, K);
        for (int j = max(j0, i + 1); j < je; j++) {
            float iw = fminf(xi1, bx1[j]) - fmaxf(xi0, bx0[j]);
            float ih = fminf(yi1, by1[j]) - fmaxf(yi0, by0[j]);
            iw = fmaxf(iw, 0.f); ih = fmaxf(ih, 0.f);
            float inter = iw * ih;
            float uni = ai + ar[j] - inter;
            float iou = __fdiv_rn(inter, fmaxf(uni, 1e-9f));
            if (iou > 0.5f) bits |= 1u << (j - j0);
        }
        mask[i * 8 + seg] = bits;
    }
    __syncthreads();

    // serial greedy scan (cheap: K ~ 72 typically)
    if (tid == 0) {
        u32 remv[8] = {0, 0, 0, 0, 0, 0, 0, 0};
        int nkeep = 0;
        for (int i = 0; i < K; i++) {
            if (!((remv[i >> 5] >> (i & 31)) & 1u)) {
                kl[nkeep++] = i;
                for (int w = 0; w < W; w++) remv[w] |= mask[i * 8 + w];
            }
        }
        sh_nk = nkeep;
        sh_base = atomicAdd(&g_poolCnt[b], nkeep);
    }
    __syncthreads();

    int nk = sh_nk, base = sh_base;
    for (int sidx = tid; sidx < nk; sidx += 128) {
        int i = kl[sidx];
        u64 kk = keys[i];
        int a = (int)(~(u32)kk) & 0xFFF;
        int flat = c * KMAX + i;                   // reference flat index for tie-break
        u64 det = (kk & 0xFFFFFFFF00000000ULL)
                | ((u64)(u32)(32767 - flat) << 17)
                | ((u64)(u32)a << 5);
        int pos = base + sidx;
        if (pos < POOLCAP) g_pool[(size_t)b * POOLCAP + pos] = det;
    }
}

// -------- kernel 3: per-image radix-select top-100 + sort + write --------
__global__ void __launch_bounds__(256) k_top(float* __restrict__ out) {
    __shared__ int hist[256];
    __shared__ int suf[257];
    __shared__ u64 sel[128];
    __shared__ int sh_cnt;
    __shared__ u64 sh_prefix;
    __shared__ int sh_rem;

    int b = blockIdx.x, tid = threadIdx.x;
    int m = g_poolCnt[b]; if (m > POOLCAP) m = POOLCAP;
    const u64* pool = g_pool + (size_t)b * POOLCAP;

    u64 kth = 0;
    if (m > 100) {
        u64 prefix = 0; int rem = 100;
        for (int pass = 0; pass < 8; pass++) {
            int shift = 56 - 8 * pass;
            hist[tid] = 0;
            __syncthreads();
            for (int i = tid; i < m; i += 256) {
                u64 kk = pool[i];
                if (pass == 0 || (kk >> (shift + 8)) == prefix)
                    atomicAdd(&hist[(int)((kk >> shift) & 0xFF)], 1);
            }
            __syncthreads();
            suf[tid] = hist[tid];
            if (tid == 0) suf[256] = 0;
            __syncthreads();
            for (int off = 1; off < 256; off <<= 1) {
                int v = (tid + off < 256) ? suf[tid + off] : 0;
                __syncthreads();
                suf[tid] += v;
                __syncthreads();
            }
            if (suf[tid] >= rem && suf[tid + 1] < rem) {   // unique digit
                sh_prefix = (prefix << 8) | (u64)tid;
                sh_rem = rem - suf[tid + 1];
            }
            __syncthreads();
            prefix = sh_prefix; rem = sh_rem;
            __syncthreads();
        }
        kth = prefix;     // exact 100th-largest key (keys are distinct)
    }

    if (tid == 0) sh_cnt = 0;
    __syncthreads();
    for (int i = tid; i < m; i += 256) {
        u64 kk = pool[i];
        if (kk >= kth) {
            int p = atomicAdd(&sh_cnt, 1);
            if (p < 128) sel[p] = kk;
        }
    }
    __syncthreads();
    int cnt = sh_cnt; if (cnt > 128) cnt = 128;
    int nsel = cnt < 100 ? cnt : 100;
    if (tid < 128 && tid >= cnt) sel[tid] = 0;
    __syncthreads();

    // bitonic sort 128 descending
    for (int k = 2; k <= 128; k <<= 1)
        for (int j = k >> 1; j > 0; j >>= 1) {
            if (tid < 128) {
                int i = tid, x = i ^ j;
                if (x > i) {
                    u64 A = sel[i], Bv = sel[x];
                    bool up = (i & k) == 0;
                    if (up ? (A < Bv) : (A > Bv)) { sel[i] = Bv; sel[x] = A; }
                }
            }
            __syncthreads();
        }

    for (int r = tid; r < 100; r += 256) {
        float o0 = 0, o1 = 0, o2 = 0, o3 = 0, o4 = 0, o5 = 0;
        if (r < nsel) {
            u64 kk = sel[r];
            float sc = __uint_as_float((u32)(kk >> 32));
            int flat = 32767 - (int)((kk >> 17) & 0x7FFF);
            int cls = flat / 200 + 1;
            int a = (int)((kk >> 5) & 0xFFF);
            float4 bb = g_boxes[b * NA + a];
            o0 = bb.x; o1 = bb.y; o2 = bb.z; o3 = bb.w; o4 = sc; o5 = (float)cls;
        }
        float* op = out + ((size_t)b * 100 + r) * 6;
        op[0] = o0; op[1] = o1; op[2] = o2; op[3] = o3; op[4] = o4; op[5] = o5;
    }
}

// -------- launch --------
extern "C" void kernel_launch(void* const* d_in, const int* in_sizes, int n_in,
                              void* d_out, int out_size) {
    const float* logits = nullptr;
    const float* boxreg = nullptr;
    const float* priors = nullptr;
    for (int i = 0; i < n_in; i++) {
        if (in_sizes[i] == BATCH * NA * NC) logits = (const float*)d_in[i];
        else if (in_sizes[i] == BATCH * NA * 4) boxreg = (const float*)d_in[i];
        else if (in_sizes[i] == NA * 4) priors = (const float*)d_in[i];
    }
    float* out = (float*)d_out;

    k_zero<<<(BATCH * CM1 + 255) / 256, 256>>>();
    k_decode<<<(BATCH * NA + 255) / 256, 256>>>(boxreg, priors);
    k_cand<<<(BATCH * NA + 7) / 8, 256>>>(logits);
    k_nms<<<dim3(CM1, BATCH), 128>>>();
    k_top<<<BATCH, 256>>>(out);
}

// round 2
// speedup vs baseline: 1.3762x; 1.3762x over previous
#include <cuda_runtime.h>
#include <stdint.h>

#define BATCH   64
#define NA      3234
#define NC      91
#define CM1     90
#define CAP     512
#define KMAX    200
#define WMAX    7
#define POOLCAP 16384

typedef unsigned long long u64;
typedef unsigned int u32;

// -------- scratch (static __device__ — no allocations allowed) --------
__device__ float4 g_boxes[BATCH * NA];                       // decoded boxes
__device__ u64    g_cand[(size_t)BATCH * CM1 * CAP];         // per (b,c) candidates > thresh
__device__ int    g_candCnt[BATCH * CM1];
__device__ u64    g_pool[(size_t)BATCH * POOLCAP];           // per image kept detections
__device__ int    g_poolCnt[BATCH];

// ~1-ulp exp, FMA-only (immune to fast-math substitution). Valid for |x| < ~80.
__device__ __forceinline__ float exp_acc(float x) {
    float k = rintf(x * 1.44269504088896340736f);
    float r = fmaf(k, -0.693359375f, x);
    r = fmaf(k, 2.12194440054690582762e-4f, r);
    float p = 1.98412698412698413e-4f;
    p = fmaf(p, r, 1.38888888888888889e-3f);
    p = fmaf(p, r, 8.33333333333333333e-3f);
    p = fmaf(p, r, 4.16666666666666667e-2f);
    p = fmaf(p, r, 1.66666666666666667e-1f);
    p = fmaf(p, r, 0.5f);
    p = fmaf(p, r, 1.0f);
    p = fmaf(p, r, 1.0f);
    int ki = (int)k;
    ki = max(-126, min(126, ki));
    return p * __int_as_float((ki + 127) << 23);
}

// -------- kernel 1a: decode boxes (+ fused counter zeroing) --------
__global__ void k_decode(const float* __restrict__ box_reg,
                         const float* __restrict__ priors) {
    int i = blockIdx.x * blockDim.x + threadIdx.x;
    if (i < BATCH * CM1) g_candCnt[i] = 0;
    if (i < BATCH) g_poolCnt[i] = 0;
    if (i >= BATCH * NA) return;
    int a = i % NA;
    float4 loc = ((const float4*)box_reg)[i];
    float4 pr  = ((const float4*)priors)[a];
    float pw = pr.z - pr.x, ph = pr.w - pr.y;
    float cx = pr.x + 0.5f * pw, cy = pr.y + 0.5f * ph;
    float x = loc.x * 0.1f * pw + cx;
    float y = loc.y * 0.1f * ph + cy;
    float w = exp_acc(loc.z * 0.2f) * pw;
    float h = exp_acc(loc.w * 0.2f) * ph;
    g_boxes[i] = make_float4(x - w * 0.5f, y - h * 0.5f, x + w * 0.5f, y + h * 0.5f);
}

// -------- kernel 1b: fused softmax + threshold filter (warp per anchor) --------
__device__ __forceinline__ void push_cand(float e, int c, int b, int a, float s, float pre) {
    if (c >= 1 && c < NC && e > pre) {
        float p = __fdiv_rn(e, s);                 // exact softmax value
        if (p > 0.05f) {
            int li = b * CM1 + (c - 1);
            int pos = atomicAdd(&g_candCnt[li], 1);
            if (pos < CAP)
                g_cand[(size_t)li * CAP + pos] =
                    ((u64)__float_as_uint(p) << 32) | (u32)(~(u32)a);
        }
    }
}

__global__ void __launch_bounds__(256) k_cand(const float* __restrict__ logits) {
    int gw = (blockIdx.x * 256 + threadIdx.x) >> 5;
    int lane = threadIdx.x & 31;
    if (gw >= BATCH * NA) return;
    int b = gw / NA;
    int a = gw - b * NA;
    const float* L = logits + (size_t)gw * NC;
    float l0 = L[lane];
    float l1 = L[lane + 32];
    float l2 = (lane < NC - 64) ? L[lane + 64] : -1e30f;
    float mx = fmaxf(l0, fmaxf(l1, l2));
#pragma unroll
    for (int o = 16; o; o >>= 1) mx = fmaxf(mx, __shfl_xor_sync(0xffffffffu, mx, o));
    float e0 = exp_acc(l0 - mx);
    float e1 = exp_acc(l1 - mx);
    float e2 = (lane < NC - 64) ? exp_acc(l2 - mx) : 0.0f;
    float s = e0 + e1 + e2;
#pragma unroll
    for (int o = 16; o; o >>= 1) s += __shfl_xor_sync(0xffffffffu, s, o);
    float pre = 0.0495f * s;   // conservative prefilter; exact test inside push_cand
    push_cand(e0, lane,      b, a, s, pre);
    push_cand(e1, lane + 32, b, a, s, pre);
    push_cand(e2, lane + 64, b, a, s, pre);
}

// -------- kernel 2: per (b,c) sort + greedy NMS --------
__global__ void __launch_bounds__(128) k_nms() {
    __shared__ u64 keys[CAP];
    __shared__ float4 sbox[KMAX];
    __shared__ float sarea[KMAX];
    __shared__ u32 mask[KMAX * WMAX];
    __shared__ int kl[KMAX];
    __shared__ int sh_nk, sh_base;

    int c = blockIdx.x, b = blockIdx.y;
    int li = b * CM1 + c;
    int m = g_candCnt[li];
    if (m > CAP) m = CAP;
    if (m == 0) return;
    int tid = threadIdx.x;

    if (m <= 128) {
        // register bitonic: one key per thread, shfl intra-warp, shared for j>=32
        u64 key = (tid < m) ? g_cand[(size_t)li * CAP + tid] : 0ULL;
#pragma unroll
        for (int k = 2; k <= 128; k <<= 1) {
#pragma unroll
            for (int j = k >> 1; j > 0; j >>= 1) {
                u64 other;
                if (j < 32) {
                    other = __shfl_xor_sync(0xffffffffu, key, j);
                } else {
                    keys[tid] = key;
                    __syncthreads();
                    other = keys[tid ^ j];
                    __syncthreads();
                }
                bool desc  = (tid & k) == 0;
                bool lower = (tid & j) == 0;
                if (desc == lower) key = (key > other) ? key : other;
                else               key = (key < other) ? key : other;
            }
        }
        keys[tid] = key;
        __syncthreads();
    } else {
        int n = 1; while (n < m) n <<= 1;       // <= 512
        for (int i = tid; i < n; i += 128)
            keys[i] = (i < m) ? g_cand[(size_t)li * CAP + i] : 0ULL;
        __syncthreads();
        for (int k = 2; k <= n; k <<= 1)
            for (int j = k >> 1; j > 0; j >>= 1) {
                for (int i = tid; i < n; i += 128) {
                    int x = i ^ j;
                    if (x > i) {
                        u64 A = keys[i], Bv = keys[x];
                        bool up = (i & k) == 0;
                        if (up ? (A < Bv) : (A > Bv)) { keys[i] = Bv; keys[x] = A; }
                    }
                }
                __syncthreads();
            }
    }

    int K = m < KMAX ? m : KMAX;
    for (int r = tid; r < K; r += 128) {
        int a = (int)(~(u32)keys[r]);
        float4 bb = g_boxes[b * NA + a];
        sbox[r] = bb;
        sarea[r] = fmaxf(bb.z - bb.x, 0.f) * fmaxf(bb.w - bb.y, 0.f);
    }
    __syncthreads();

    // IoU suppression bitmatrix (j > i); exact divide only near threshold
    int W = (K + 31) >> 5;
    for (int w = tid; w < K * W; w += 128) {
        int i = w / W, seg = w - i * W;
        u32 bits = 0;
        float4 bi = sbox[i];
        float ai = sarea[i];
        int j0 = seg << 5;
        int je = min(j0 + 32, K);
        for (int j = max(j0, i + 1); j < je; j++) {
            float4 bj = sbox[j];
            float iw = fminf(bi.z, bj.z) - fmaxf(bi.x, bj.x);
            float ih = fminf(bi.w, bj.w) - fmaxf(bi.y, bj.y);
            iw = fmaxf(iw, 0.f); ih = fmaxf(ih, 0.f);
            float inter = iw * ih;
            float uni = ai + sarea[j] - inter;
            if (inter > 0.4985f * uni) {   // superset filter; exact decision below
                if (__fdiv_rn(inter, fmaxf(uni, 1e-9f)) > 0.5f)
                    bits |= 1u << (j - j0);
            }
        }
        mask[i * W + seg] = bits;
    }
    __syncthreads();

    // serial greedy scan (K ~ 72 typically)
    if (tid == 0) {
        u32 remv[WMAX] = {0, 0, 0, 0, 0, 0, 0};
        int nkeep = 0;
        for (int i = 0; i < K; i++) {
            if (!((remv[i >> 5] >> (i & 31)) & 1u)) {
                kl[nkeep++] = i;
                for (int w = 0; w < W; w++) remv[w] |= mask[i * W + w];
            }
        }
        sh_nk = nkeep;
        sh_base = atomicAdd(&g_poolCnt[b], nkeep);
    }
    __syncthreads();

    int nk = sh_nk, base = sh_base;
    for (int sidx = tid; sidx < nk; sidx += 128) {
        int i = kl[sidx];
        u64 kk = keys[i];
        int a = (int)(~(u32)kk) & 0xFFF;
        int flat = c * KMAX + i;                   // reference flat index for tie-break
        u64 det = (kk & 0xFFFFFFFF00000000ULL)
                | ((u64)(u32)(32767 - flat) << 17)
                | ((u64)(u32)a << 5);
        int pos = base + sidx;
        if (pos < POOLCAP) g_pool[(size_t)b * POOLCAP + pos] = det;
    }
}

// -------- kernel 3: per-image 12-bit radix-select top-100 + sort + write --------
__global__ void __launch_bounds__(256) k_top(float* __restrict__ out) {
    __shared__ int hist[4096];
    __shared__ int segs[256];
    __shared__ u64 sel[128];
    __shared__ int sh_cnt;
    __shared__ u64 sh_prefix;
    __shared__ int sh_rem;

    int b = blockIdx.x, tid = threadIdx.x;
    int m = g_poolCnt[b]; if (m > POOLCAP) m = POOLCAP;
    const u64* pool = g_pool + (size_t)b * POOLCAP;

    u64 kth = 0;
    if (m > 100) {
        u64 prefix = 0; int rem = 100;
        // 4 passes x 12 bits over bits [63:16]. Top-48 prefix is unique per key
        // (flat-index field lives in bits [31:17]), so the threshold is exact.
#pragma unroll
        for (int pass = 0; pass < 4; pass++) {
            int shift = 52 - 12 * pass;
            for (int d = tid; d < 4096; d += 256) hist[d] = 0;
            __syncthreads();
            for (int i = tid; i < m; i += 256) {
                u64 kk = pool[i];
                if (pass == 0 || (kk >> (shift + 12)) == prefix)
                    atomicAdd(&hist[(int)((kk >> shift) & 0xFFF)], 1);
            }
            __syncthreads();
            // two-level suffix scan: segments of 16 bins per thread
            int s = 0;
#pragma unroll
            for (int q = 0; q < 16; q++) s += hist[tid * 16 + q];
            segs[tid] = s;
            __syncthreads();
            for (int off = 1; off < 256; off <<= 1) {
                int v = (tid + off < 256) ? segs[tid + off] : 0;
                __syncthreads();
                segs[tid] += v;
                __syncthreads();
            }
            // segs[t] = sum over digits >= 16t. Find crossing digit in own segment.
            int run = (tid < 255) ? segs[tid + 1] : 0;
#pragma unroll
            for (int q = 15; q >= 0; q--) {
                int d = tid * 16 + q;
                int ge = run + hist[d];
                if (ge >= rem && run < rem) {
                    sh_prefix = (prefix << 12) | (u64)d;
                    sh_rem = rem - run;
                }
                run = ge;
            }
            __syncthreads();
            prefix = sh_prefix; rem = sh_rem;
            __syncthreads();
        }
        kth = prefix << 16;     // exact 100th-largest key threshold
    }

    if (tid == 0) sh_cnt = 0;
    __syncthreads();
    for (int i = tid; i < m; i += 256) {
        u64 kk = pool[i];
        if (kk >= kth) {
            int p = atomicAdd(&sh_cnt, 1);
            if (p < 128) sel[p] = kk;
        }
    }
    __syncthreads();
    int cnt = sh_cnt; if (cnt > 128) cnt = 128;
    int nsel = cnt < 100 ? cnt : 100;
    if (tid < 128 && tid >= cnt) sel[tid] = 0;
    __syncthreads();

    // bitonic sort 128 descending
    for (int k = 2; k <= 128; k <<= 1)
        for (int j = k >> 1; j > 0; j >>= 1) {
            if (tid < 128) {
                int i = tid, x = i ^ j;
                if (x > i) {
                    u64 A = sel[i], Bv = sel[x];
                    bool up = (i & k) == 0;
                    if (up ? (A < Bv) : (A > Bv)) { sel[i] = Bv; sel[x] = A; }
                }
            }
            __syncthreads();
        }

    for (int r = tid; r < 100; r += 256) {
        float o0 = 0, o1 = 0, o2 = 0, o3 = 0, o4 = 0, o5 = 0;
        if (r < nsel) {
            u64 kk = sel[r];
            float sc = __uint_as_float((u32)(kk >> 32));
            int flat = 32767 - (int)((kk >> 17) & 0x7FFF);
            int cls = flat / 200 + 1;
            int a = (int)((kk >> 5) & 0xFFF);
            float4 bb = g_boxes[b * NA + a];
            o0 = bb.x; o1 = bb.y; o2 = bb.z; o3 = bb.w; o4 = sc; o5 = (float)cls;
        }
        float* op = out + ((size_t)b * 100 + r) * 6;
        op[0] = o0; op[1] = o1; op[2] = o2; op[3] = o3; op[4] = o4; op[5] = o5;
    }
}

// -------- launch --------
extern "C" void kernel_launch(void* const* d_in, const int* in_sizes, int n_in,
                              void* d_out, int out_size) {
    const float* logits = nullptr;
    const float* boxreg = nullptr;
    const float* priors = nullptr;
    for (int i = 0; i < n_in; i++) {
        if (in_sizes[i] == BATCH * NA * NC) logits = (const float*)d_in[i];
        else if (in_sizes[i] == BATCH * NA * 4) boxreg = (const float*)d_in[i];
        else if (in_sizes[i] == NA * 4) priors = (const float*)d_in[i];
    }
    float* out = (float*)d_out;

    k_decode<<<(BATCH * NA + 255) / 256, 256>>>(boxreg, priors);
    k_cand<<<(BATCH * NA + 7) / 8, 256>>>(logits);
    k_nms<<<dim3(CM1, BATCH), 128>>>();
    k_top<<<BATCH, 256>>>(out);
}

// round 3
// speedup vs baseline: 1.7759x; 1.2905x over previous
#include <cuda_runtime.h>
#include <stdint.h>

#define BATCH   64
#define NA      3234
#define NC      91
#define CM1     90
#define CAP     512
#define KMAX    200
#define WMAX    7
#define POOLCAP 16384

typedef unsigned long long u64;
typedef unsigned int u32;

// -------- scratch (static __device__ — no allocations allowed) --------
__device__ float4 g_boxes[BATCH * NA];
__device__ u64    g_cand[(size_t)BATCH * CM1 * CAP];
__device__ int    g_candCnt[BATCH * CM1];
__device__ u64    g_pool[(size_t)BATCH * POOLCAP];
__device__ int    g_poolCnt[BATCH];
__device__ int    g_bigCnt;
__device__ int    g_bigList[BATCH * CM1];

// ~1-ulp exp, FMA-only (immune to fast-math substitution).
__device__ __forceinline__ float exp_acc(float x) {
    float k = rintf(x * 1.44269504088896340736f);
    float r = fmaf(k, -0.693359375f, x);
    r = fmaf(k, 2.12194440054690582762e-4f, r);
    float p = 1.98412698412698413e-4f;
    p = fmaf(p, r, 1.38888888888888889e-3f);
    p = fmaf(p, r, 8.33333333333333333e-3f);
    p = fmaf(p, r, 4.16666666666666667e-2f);
    p = fmaf(p, r, 1.66666666666666667e-1f);
    p = fmaf(p, r, 0.5f);
    p = fmaf(p, r, 1.0f);
    p = fmaf(p, r, 1.0f);
    int ki = (int)k;
    ki = max(-126, min(126, ki));
    return p * __int_as_float((ki + 127) << 23);
}

// -------- kernel 1a: decode boxes (+ fused counter zeroing) --------
__global__ void k_decode(const float* __restrict__ box_reg,
                         const float* __restrict__ priors) {
    int i = blockIdx.x * blockDim.x + threadIdx.x;
    if (i < BATCH * CM1) g_candCnt[i] = 0;
    if (i < BATCH) g_poolCnt[i] = 0;
    if (i == 0) g_bigCnt = 0;
    if (i >= BATCH * NA) return;
    int a = i % NA;
    float4 loc = ((const float4*)box_reg)[i];
    float4 pr  = ((const float4*)priors)[a];
    float pw = pr.z - pr.x, ph = pr.w - pr.y;
    float cx = pr.x + 0.5f * pw, cy = pr.y + 0.5f * ph;
    float x = loc.x * 0.1f * pw + cx;
    float y = loc.y * 0.1f * ph + cy;
    float w = exp_acc(loc.z * 0.2f) * pw;
    float h = exp_acc(loc.w * 0.2f) * ph;
    g_boxes[i] = make_float4(x - w * 0.5f, y - h * 0.5f, x + w * 0.5f, y + h * 0.5f);
}

// -------- kernel 1b: fused softmax + threshold filter (warp per anchor) --------
__device__ __forceinline__ void push_cand(float e, int c, int b, int a, float s, float pre) {
    if (c >= 1 && c < NC && e > pre) {
        float p = __fdiv_rn(e, s);
        if (p > 0.05f) {
            int li = b * CM1 + (c - 1);
            int pos = atomicAdd(&g_candCnt[li], 1);
            if (pos < CAP)
                g_cand[(size_t)li * CAP + pos] =
                    ((u64)__float_as_uint(p) << 32) | (u32)(~(u32)a);
        }
    }
}

__global__ void __launch_bounds__(256) k_cand(const float* __restrict__ logits) {
    int gw = (blockIdx.x * 256 + threadIdx.x) >> 5;
    int lane = threadIdx.x & 31;
    if (gw >= BATCH * NA) return;
    int b = gw / NA;
    int a = gw - b * NA;
    const float* L = logits + (size_t)gw * NC;
    float l0 = L[lane];
    float l1 = L[lane + 32];
    float l2 = (lane < NC - 64) ? L[lane + 64] : -1e30f;
    float mx = fmaxf(l0, fmaxf(l1, l2));
#pragma unroll
    for (int o = 16; o; o >>= 1) mx = fmaxf(mx, __shfl_xor_sync(0xffffffffu, mx, o));
    float e0 = exp_acc(l0 - mx);
    float e1 = exp_acc(l1 - mx);
    float e2 = (lane < NC - 64) ? exp_acc(l2 - mx) : 0.0f;
    float s = e0 + e1 + e2;
#pragma unroll
    for (int o = 16; o; o >>= 1) s += __shfl_xor_sync(0xffffffffu, s, o);
    float pre = 0.0495f * s;
    push_cand(e0, lane,      b, a, s, pre);
    push_cand(e1, lane + 32, b, a, s, pre);
    push_cand(e2, lane + 64, b, a, s, pre);
}

// -------- kernel 2: warp-per-class NMS (m <= 128 fast path) --------
__global__ void __launch_bounds__(128) k_nms_warp() {
    // per-warp shared regions
    __shared__ float4 sbox[4][128];
    __shared__ float  sarea[4][128];
    __shared__ u32    smask[4][128 * 4];

    int wid = threadIdx.x >> 5;
    int lane = threadIdx.x & 31;
    int li = blockIdx.x * 4 + wid;
    if (li >= BATCH * CM1) return;
    int b = li / CM1;
    int c = li - b * CM1;

    int m = g_candCnt[li];
    if (m == 0) return;
    if (m > 128) {                         // rare fallback to block kernel
        if (lane == 0) {
            int p = atomicAdd(&g_bigCnt, 1);
            g_bigList[p] = li;
        }
        return;
    }

    // load keys: element e = r*32 + lane
    u64 key[4];
#pragma unroll
    for (int r = 0; r < 4; r++) {
        int e = r * 32 + lane;
        key[r] = (e < m) ? g_cand[(size_t)li * CAP + e] : 0ULL;
    }

    // register bitonic sort, 128 elements, descending
#pragma unroll
    for (int k = 2; k <= 128; k <<= 1) {
#pragma unroll
        for (int j = k >> 1; j > 0; j >>= 1) {
            if (j >= 32) {
                int rj = j >> 5;
#pragma unroll
                for (int r = 0; r < 4; r++) {
                    if ((r & rj) == 0) {
                        int rp = r | rj;
                        int e = r * 32 + lane;
                        bool desc = ((e & k) == 0);
                        u64 A = key[r], Bv = key[rp];
                        if (desc ? (A < Bv) : (A > Bv)) { key[r] = Bv; key[rp] = A; }
                    }
                }
            } else {
#pragma unroll
                for (int r = 0; r < 4; r++) {
                    u64 other = __shfl_xor_sync(0xffffffffu, key[r], j);
                    int e = r * 32 + lane;
                    bool desc = ((e & k) == 0);
                    bool lower = ((lane & j) == 0);
                    if (desc == lower) key[r] = (key[r] > other) ? key[r] : other;
                    else               key[r] = (key[r] < other) ? key[r] : other;
                }
            }
        }
    }

    int K = m;   // m <= 128 <= KMAX

    // stage boxes + areas in per-warp shared
#pragma unroll
    for (int r = 0; r < 4; r++) {
        int e = r * 32 + lane;
        if (e < K) {
            int a = (int)(~(u32)key[r]);
            float4 bb = g_boxes[b * NA + a];
            sbox[wid][e] = bb;
            sarea[wid][e] = fmaxf(bb.z - bb.x, 0.f) * fmaxf(bb.w - bb.y, 0.f);
        }
    }
    __syncwarp();

    // suppression rows: lane owns rows lane, lane+32, lane+64, lane+96
#pragma unroll
    for (int r = 0; r < 4; r++) {
        int i = r * 32 + lane;
        if (i < K) {
            u32 w0 = 0, w1 = 0, w2 = 0, w3 = 0;
            float4 bi = sbox[wid][i];
            float ai = sarea[wid][i];
            for (int j = i + 1; j < K; j++) {
                float4 bj = sbox[wid][j];
                float iw = fminf(bi.z, bj.z) - fmaxf(bi.x, bj.x);
                float ih = fminf(bi.w, bj.w) - fmaxf(bi.y, bj.y);
                iw = fmaxf(iw, 0.f); ih = fmaxf(ih, 0.f);
                float inter = iw * ih;
                float uni = ai + sarea[wid][j] - inter;
                bool sup = false;
                if (inter > 0.4985f * uni)        // superset prefilter
                    sup = __fdiv_rn(inter, fmaxf(uni, 1e-9f)) > 0.5f;
                if (sup) {
                    u32 bit = 1u << (j & 31);
                    switch (j >> 5) {
                        case 0: w0 |= bit; break;
                        case 1: w1 |= bit; break;
                        case 2: w2 |= bit; break;
                        default: w3 |= bit; break;
                    }
                }
            }
            smask[wid][i * 4 + 0] = w0;
            smask[wid][i * 4 + 1] = w1;
            smask[wid][i * 4 + 2] = w2;
            smask[wid][i * 4 + 3] = w3;
        }
    }
    __syncwarp();

    // lane 0: greedy scan over alive bitmask (nkeep iterations only)
    u32 kw0 = 0, kw1 = 0, kw2 = 0, kw3 = 0;
    int base = 0;
    if (lane == 0) {
        u32 rem[4];
#pragma unroll
        for (int w = 0; w < 4; w++) {
            int lo = w * 32;
            rem[w] = (K >= lo + 32) ? 0xffffffffu : (K > lo ? ((1u << (K - lo)) - 1u) : 0u);
        }
        u32 kw[4] = {0, 0, 0, 0};
#pragma unroll
        for (int w = 0; w < 4; w++) {
            while (rem[w]) {
                int bit = __ffs(rem[w]) - 1;
                int i = w * 32 + bit;
                kw[w] |= 1u << bit;
                rem[w] &= ~(1u << bit);
                const u32* row = &smask[wid][i * 4];
                rem[0] &= ~row[0]; rem[1] &= ~row[1];
                rem[2] &= ~row[2]; rem[3] &= ~row[3];
            }
        }
        int nkeep = __popc(kw[0]) + __popc(kw[1]) + __popc(kw[2]) + __popc(kw[3]);
        base = atomicAdd(&g_poolCnt[b], nkeep);
        kw0 = kw[0]; kw1 = kw[1]; kw2 = kw[2]; kw3 = kw[3];
    }
    kw0 = __shfl_sync(0xffffffffu, kw0, 0);
    kw1 = __shfl_sync(0xffffffffu, kw1, 0);
    kw2 = __shfl_sync(0xffffffffu, kw2, 0);
    kw3 = __shfl_sync(0xffffffffu, kw3, 0);
    base = __shfl_sync(0xffffffffu, base, 0);

    u32 kwarr0 = kw0, kwarr1 = kw1, kwarr2 = kw2, kwarr3 = kw3;
    int pre0 = 0;
    int pre1 = __popc(kwarr0);
    int pre2 = pre1 + __popc(kwarr1);
    int pre3 = pre2 + __popc(kwarr2);
#pragma unroll
    for (int r = 0; r < 4; r++) {
        int e = r * 32 + lane;      // e>>5 == r
        u32 kwr = (r == 0) ? kwarr0 : (r == 1) ? kwarr1 : (r == 2) ? kwarr2 : kwarr3;
        int prer = (r == 0) ? pre0 : (r == 1) ? pre1 : (r == 2) ? pre2 : pre3;
        if (e < K && ((kwr >> lane) & 1u)) {
            int rank = prer + __popc(kwr & ((1u << lane) - 1u));
            u64 kk = key[r];
            int a = (int)(~(u32)kk) & 0xFFF;
            int flat = c * KMAX + e;
            u64 det = (kk & 0xFFFFFFFF00000000ULL)
                    | ((u64)(u32)(32767 - flat) << 17)
                    | ((u64)(u32)a << 5);
            int pos = base + rank;
            if (pos < POOLCAP) g_pool[(size_t)b * POOLCAP + pos] = det;
        }
    }
}

// -------- kernel 2b: block-level fallback for m > 128 (rare) --------
__global__ void __launch_bounds__(128) k_nms_big() {
    __shared__ u64 keys[CAP];
    __shared__ float4 sbox[KMAX];
    __shared__ float sarea[KMAX];
    __shared__ u32 mask[KMAX * WMAX];
    __shared__ int kl[KMAX];
    __shared__ int sh_nk, sh_base;

    int nbig = g_bigCnt;
    for (int idx = blockIdx.x; idx < nbig; idx += gridDim.x) {
        int li = g_bigList[idx];
        int b = li / CM1;
        int c = li - b * CM1;
        int m = g_candCnt[li];
        if (m > CAP) m = CAP;
        int tid = threadIdx.x;

        int n = 1; while (n < m) n <<= 1;
        for (int i = tid; i < n; i += 128)
            keys[i] = (i < m) ? g_cand[(size_t)li * CAP + i] : 0ULL;
        __syncthreads();
        for (int k = 2; k <= n; k <<= 1)
            for (int j = k >> 1; j > 0; j >>= 1) {
                for (int i = tid; i < n; i += 128) {
                    int x = i ^ j;
                    if (x > i) {
                        u64 A = keys[i], Bv = keys[x];
                        bool up = (i & k) == 0;
                        if (up ? (A < Bv) : (A > Bv)) { keys[i] = Bv; keys[x] = A; }
                    }
                }
                __syncthreads();
            }

        int K = m < KMAX ? m : KMAX;
        for (int r = tid; r < K; r += 128) {
            int a = (int)(~(u32)keys[r]);
            float4 bb = g_boxes[b * NA + a];
            sbox[r] = bb;
            sarea[r] = fmaxf(bb.z - bb.x, 0.f) * fmaxf(bb.w - bb.y, 0.f);
        }
        __syncthreads();

        int W = (K + 31) >> 5;
        for (int w = tid; w < K * W; w += 128) {
            int i = w / W, seg = w - i * W;
            u32 bits = 0;
            float4 bi = sbox[i];
            float ai = sarea[i];
            int j0 = seg << 5;
            int je = min(j0 + 32, K);
            for (int j = max(j0, i + 1); j < je; j++) {
                float4 bj = sbox[j];
                float iw = fminf(bi.z, bj.z) - fmaxf(bi.x, bj.x);
                float ih = fminf(bi.w, bj.w) - fmaxf(bi.y, bj.y);
                iw = fmaxf(iw, 0.f); ih = fmaxf(ih, 0.f);
                float inter = iw * ih;
                float uni = ai + sarea[j] - inter;
                if (inter > 0.4985f * uni)
                    if (__fdiv_rn(inter, fmaxf(uni, 1e-9f)) > 0.5f)
                        bits |= 1u << (j - j0);
            }
            mask[i * W + seg] = bits;
        }
        __syncthreads();

        if (tid == 0) {
            u32 remv[WMAX] = {0, 0, 0, 0, 0, 0, 0};
            int nkeep = 0;
            for (int i = 0; i < K; i++) {
                if (!((remv[i >> 5] >> (i & 31)) & 1u)) {
                    kl[nkeep++] = i;
                    for (int w = 0; w < W; w++) remv[w] |= mask[i * W + w];
                }
            }
            sh_nk = nkeep;
            sh_base = atomicAdd(&g_poolCnt[b], nkeep);
        }
        __syncthreads();

        int nk = sh_nk, bse = sh_base;
        for (int sidx = tid; sidx < nk; sidx += 128) {
            int i = kl[sidx];
            u64 kk = keys[i];
            int a = (int)(~(u32)kk) & 0xFFF;
            int flat = c * KMAX + i;
            u64 det = (kk & 0xFFFFFFFF00000000ULL)
                    | ((u64)(u32)(32767 - flat) << 17)
                    | ((u64)(u32)a << 5);
            int pos = bse + sidx;
            if (pos < POOLCAP) g_pool[(size_t)b * POOLCAP + pos] = det;
        }
        __syncthreads();
    }
}

// -------- kernel 3: per-image 12-bit radix-select top-100 (1024 threads) --------
__global__ void __launch_bounds__(1024) k_top(float* __restrict__ out) {
    __shared__ int hist[4096];
    __shared__ int segs[256];
    __shared__ u64 sel[128];
    __shared__ int sh_cnt;
    __shared__ u64 sh_prefix;
    __shared__ int sh_rem;

    int b = blockIdx.x, tid = threadIdx.x;
    int m = g_poolCnt[b]; if (m > POOLCAP) m = POOLCAP;
    const u64* pool = g_pool + (size_t)b * POOLCAP;

    u64 kth = 0;
    if (m > 100) {
        u64 prefix = 0; int rem = 100;
#pragma unroll
        for (int pass = 0; pass < 4; pass++) {
            int shift = 52 - 12 * pass;
            for (int d = tid; d < 4096; d += 1024) hist[d] = 0;
            __syncthreads();
            for (int i = tid; i < m; i += 1024) {
                u64 kk = pool[i];
                if (pass == 0 || (kk >> (shift + 12)) == prefix)
                    atomicAdd(&hist[(int)((kk >> shift) & 0xFFF)], 1);
            }
            __syncthreads();
            if (tid < 256) {
                int s = 0;
#pragma unroll
                for (int q = 0; q < 16; q++) s += hist[tid * 16 + q];
                segs[tid] = s;
            }
            __syncthreads();
            for (int off = 1; off < 256; off <<= 1) {
                int v = 0;
                if (tid < 256 && tid + off < 256) v = segs[tid + off];
                __syncthreads();
                if (tid < 256) segs[tid] += v;
                __syncthreads();
            }
            if (tid < 256) {
                int run = (tid < 255) ? segs[tid + 1] : 0;
#pragma unroll
                for (int q = 15; q >= 0; q--) {
                    int d = tid * 16 + q;
                    int ge = run + hist[d];
                    if (ge >= rem && run < rem) {
                        sh_prefix = (prefix << 12) | (u64)d;
                        sh_rem = rem - run;
                    }
                    run = ge;
                }
            }
            __syncthreads();
            prefix = sh_prefix; rem = sh_rem;
            __syncthreads();
        }
        kth = prefix << 16;     // top-48 prefix unique per key -> exact threshold
    }

    if (tid == 0) sh_cnt = 0;
    __syncthreads();
    for (int i = tid; i < m; i += 1024) {
        u64 kk = pool[i];
        if (kk >= kth) {
            int p = atomicAdd(&sh_cnt, 1);
            if (p < 128) sel[p] = kk;
        }
    }
    __syncthreads();
    int cnt = sh_cnt; if (cnt > 128) cnt = 128;
    int nsel = cnt < 100 ? cnt : 100;
    if (tid < 128 && tid >= cnt) sel[tid] = 0;
    __syncthreads();

    for (int k = 2; k <= 128; k <<= 1)
        for (int j = k >> 1; j > 0; j >>= 1) {
            if (tid < 128) {
                int i = tid, x = i ^ j;
                if (x > i) {
                    u64 A = sel[i], Bv = sel[x];
                    bool up = (i & k) == 0;
                    if (up ? (A < Bv) : (A > Bv)) { sel[i] = Bv; sel[x] = A; }
                }
            }
            __syncthreads();
        }

    for (int r = tid; r < 100; r += 1024) {
        float o0 = 0, o1 = 0, o2 = 0, o3 = 0, o4 = 0, o5 = 0;
        if (r < nsel) {
            u64 kk = sel[r];
            float sc = __uint_as_float((u32)(kk >> 32));
            int flat = 32767 - (int)((kk >> 17) & 0x7FFF);
            int cls = flat / 200 + 1;
            int a = (int)((kk >> 5) & 0xFFF);
            float4 bb = g_boxes[b * NA + a];
            o0 = bb.x; o1 = bb.y; o2 = bb.z; o3 = bb.w; o4 = sc; o5 = (float)cls;
        }
        float* op = out + ((size_t)b * 100 + r) * 6;
        op[0] = o0; op[1] = o1; op[2] = o2; op[3] = o3; op[4] = o4; op[5] = o5;
    }
}

// -------- launch --------
extern "C" void kernel_launch(void* const* d_in, const int* in_sizes, int n_in,
                              void* d_out, int out_size) {
    const float* logits = nullptr;
    const float* boxreg = nullptr;
    const float* priors = nullptr;
    for (int i = 0; i < n_in; i++) {
        if (in_sizes[i] == BATCH * NA * NC) logits = (const float*)d_in[i];
        else if (in_sizes[i] == BATCH * NA * 4) boxreg = (const float*)d_in[i];
        else if (in_sizes[i] == NA * 4) priors = (const float*)d_in[i];
    }
    float* out = (float*)d_out;

    k_decode<<<(BATCH * NA + 255) / 256, 256>>>(boxreg, priors);
    k_cand<<<(BATCH * NA + 7) / 8, 256>>>(logits);
    k_nms_warp<<<(BATCH * CM1 + 3) / 4, 128>>>();
    k_nms_big<<<32, 128>>>();
    k_top<<<BATCH, 1024>>>(out);
}

// round 4
// speedup vs baseline: 1.8624x; 1.0487x over previous
#include <cuda_runtime.h>
#include <stdint.h>

#define BATCH   64
#define NA      3234
#define NC      91
#define CM1     90
#define CAP     512
#define KMAX    200
#define WMAX    7
#define POOLCAP 16384

typedef unsigned long long u64;
typedef unsigned int u32;

// -------- scratch (static __device__ — no allocations allowed) --------
__device__ float4 g_boxes[BATCH * NA];
__device__ u64    g_cand[(size_t)BATCH * CM1 * CAP];
__device__ int    g_candCnt[BATCH * CM1];
__device__ u64    g_pool[(size_t)BATCH * POOLCAP];
__device__ int    g_poolCnt[BATCH];
__device__ int    g_bigCnt;
__device__ int    g_bigList[BATCH * CM1];

// ~1-ulp exp, FMA-only (immune to fast-math substitution).
__device__ __forceinline__ float exp_acc(float x) {
    float k = rintf(x * 1.44269504088896340736f);
    float r = fmaf(k, -0.693359375f, x);
    r = fmaf(k, 2.12194440054690582762e-4f, r);
    float p = 1.98412698412698413e-4f;
    p = fmaf(p, r, 1.38888888888888889e-3f);
    p = fmaf(p, r, 8.33333333333333333e-3f);
    p = fmaf(p, r, 4.16666666666666667e-2f);
    p = fmaf(p, r, 1.66666666666666667e-1f);
    p = fmaf(p, r, 0.5f);
    p = fmaf(p, r, 1.0f);
    p = fmaf(p, r, 1.0f);
    int ki = (int)k;
    ki = max(-126, min(126, ki));
    return p * __int_as_float((ki + 127) << 23);
}

// order-preserving float -> u32 map (exact; for redux-based max)
__device__ __forceinline__ u32 f2ord(float x) {
    u32 u = __float_as_uint(x);
    return (u & 0x80000000u) ? ~u : (u | 0x80000000u);
}
__device__ __forceinline__ float ord2f(u32 k) {
    u32 u = (k & 0x80000000u) ? (k ^ 0x80000000u) : ~k;
    return __uint_as_float(u);
}

// -------- kernel 1a: decode boxes (+ fused counter zeroing) --------
__global__ void k_decode(const float* __restrict__ box_reg,
                         const float* __restrict__ priors) {
    int i = blockIdx.x * blockDim.x + threadIdx.x;
    if (i < BATCH * CM1) g_candCnt[i] = 0;
    if (i < BATCH) g_poolCnt[i] = 0;
    if (i == 0) g_bigCnt = 0;
    if (i >= BATCH * NA) return;
    int a = i % NA;
    float4 loc = ((const float4*)box_reg)[i];
    float4 pr  = ((const float4*)priors)[a];
    float pw = pr.z - pr.x, ph = pr.w - pr.y;
    float cx = pr.x + 0.5f * pw, cy = pr.y + 0.5f * ph;
    float x = loc.x * 0.1f * pw + cx;
    float y = loc.y * 0.1f * ph + cy;
    float w = exp_acc(loc.z * 0.2f) * pw;
    float h = exp_acc(loc.w * 0.2f) * ph;
    g_boxes[i] = make_float4(x - w * 0.5f, y - h * 0.5f, x + w * 0.5f, y + h * 0.5f);
}

// -------- kernel 1b: fused softmax + threshold filter (warp per anchor) --------
__device__ __forceinline__ void push_cand(float e, int c, int b, int a, float s, float pre) {
    if (c >= 1 && c < NC && e > pre) {
        float p = __fdiv_rn(e, s);
        if (p > 0.05f) {
            int li = b * CM1 + (c - 1);
            int pos = atomicAdd(&g_candCnt[li], 1);
            if (pos < CAP)
                g_cand[(size_t)li * CAP + pos] =
                    ((u64)__float_as_uint(p) << 32) | (u32)(~(u32)a);
        }
    }
}

__global__ void __launch_bounds__(256) k_cand(const float* __restrict__ logits) {
    int gw = (blockIdx.x * 256 + threadIdx.x) >> 5;
    int lane = threadIdx.x & 31;
    if (gw >= BATCH * NA) return;
    int b = gw / NA;
    int a = gw - b * NA;
    const float* L = logits + (size_t)gw * NC;
    float l0 = L[lane];
    float l1 = L[lane + 32];
    float l2 = (lane < NC - 64) ? L[lane + 64] : -1e30f;
    // exact max via single redux on order-preserving u32 map
    u32 om = max(f2ord(l0), max(f2ord(l1), f2ord(l2)));
    float mx = ord2f(__reduce_max_sync(0xffffffffu, om));
    float e0 = exp_acc(l0 - mx);
    float e1 = exp_acc(l1 - mx);
    float e2 = (lane < NC - 64) ? exp_acc(l2 - mx) : 0.0f;
    float s = e0 + e1 + e2;
#pragma unroll
    for (int o = 16; o; o >>= 1) s += __shfl_xor_sync(0xffffffffu, s, o);
    float pre = 0.0495f * s;
    push_cand(e0, lane,      b, a, s, pre);
    push_cand(e1, lane + 32, b, a, s, pre);
    push_cand(e2, lane + 64, b, a, s, pre);
}

// -------- kernel 2: warp-per-class NMS (m <= 128 fast path) --------
__global__ void __launch_bounds__(128) k_nms_warp() {
    __shared__ float4 sbox[4][128];
    __shared__ float  sarea[4][128];
    __shared__ u32    smask[4][128 * 4];

    int wid = threadIdx.x >> 5;
    int lane = threadIdx.x & 31;
    int li = blockIdx.x * 4 + wid;
    if (li >= BATCH * CM1) return;
    int b = li / CM1;
    int c = li - b * CM1;

    int m = g_candCnt[li];
    if (m == 0) return;
    if (m > 128) {                         // rare fallback, handled in k_top
        if (lane == 0) {
            int p = atomicAdd(&g_bigCnt, 1);
            g_bigList[p] = li;
        }
        return;
    }

    u64 key[4];
#pragma unroll
    for (int r = 0; r < 4; r++) {
        int e = r * 32 + lane;
        key[r] = (e < m) ? g_cand[(size_t)li * CAP + e] : 0ULL;
    }

    // register bitonic sort, 128 elements, descending
#pragma unroll
    for (int k = 2; k <= 128; k <<= 1) {
#pragma unroll
        for (int j = k >> 1; j > 0; j >>= 1) {
            if (j >= 32) {
                int rj = j >> 5;
#pragma unroll
                for (int r = 0; r < 4; r++) {
                    if ((r & rj) == 0) {
                        int rp = r | rj;
                        int e = r * 32 + lane;
                        bool desc = ((e & k) == 0);
                        u64 A = key[r], Bv = key[rp];
                        if (desc ? (A < Bv) : (A > Bv)) { key[r] = Bv; key[rp] = A; }
                    }
                }
            } else {
#pragma unroll
                for (int r = 0; r < 4; r++) {
                    u64 other = __shfl_xor_sync(0xffffffffu, key[r], j);
                    int e = r * 32 + lane;
                    bool desc = ((e & k) == 0);
                    bool lower = ((lane & j) == 0);
                    if (desc == lower) key[r] = (key[r] > other) ? key[r] : other;
                    else               key[r] = (key[r] < other) ? key[r] : other;
                }
            }
        }
    }

    int K = m;   // <= 128 <= KMAX

#pragma unroll
    for (int r = 0; r < 4; r++) {
        int e = r * 32 + lane;
        if (e < K) {
            int a = (int)(~(u32)key[r]);
            float4 bb = g_boxes[b * NA + a];
            sbox[wid][e] = bb;
            sarea[wid][e] = fmaxf(bb.z - bb.x, 0.f) * fmaxf(bb.w - bb.y, 0.f);
        }
    }
    __syncwarp();

    // suppression rows, seg-chunked mask accumulation
    int lastseg = (K - 1) >> 5;
#pragma unroll
    for (int r = 0; r < 4; r++) {
        int i = r * 32 + lane;
        if (i < K) {
            float4 bi = sbox[wid][i];
            float ai = sarea[wid][i];
#pragma unroll
            for (int seg = 0; seg < 4; seg++) {
                u32 bits = 0;
                if (seg <= lastseg) {
                    int j0 = seg << 5; if (j0 < i + 1) j0 = i + 1;
                    int je = (seg << 5) + 32; if (je > K) je = K;
                    for (int j = j0; j < je; j++) {
                        float4 bj = sbox[wid][j];
                        float iw = fminf(bi.z, bj.z) - fmaxf(bi.x, bj.x);
                        float ih = fminf(bi.w, bj.w) - fmaxf(bi.y, bj.y);
                        iw = fmaxf(iw, 0.f); ih = fmaxf(ih, 0.f);
                        float inter = iw * ih;
                        float uni = ai + sarea[wid][j] - inter;
                        if (inter > 0.4985f * uni)                // superset prefilter
                            if (__fdiv_rn(inter, fmaxf(uni, 1e-9f)) > 0.5f)
                                bits |= 1u << (j & 31);
                    }
                }
                smask[wid][i * 4 + seg] = bits;
            }
        }
    }
    __syncwarp();

    // lane 0: greedy scan over alive bitmask
    u32 kw0 = 0, kw1 = 0, kw2 = 0, kw3 = 0;
    int base = 0;
    if (lane == 0) {
        u32 rem[4];
#pragma unroll
        for (int w = 0; w < 4; w++) {
            int lo = w * 32;
            rem[w] = (K >= lo + 32) ? 0xffffffffu : (K > lo ? ((1u << (K - lo)) - 1u) : 0u);
        }
        u32 kw[4] = {0, 0, 0, 0};
#pragma unroll
        for (int w = 0; w < 4; w++) {
            while (rem[w]) {
                int bit = __ffs(rem[w]) - 1;
                int i = w * 32 + bit;
                kw[w] |= 1u << bit;
                rem[w] &= ~(1u << bit);
                const u32* row = &smask[wid][i * 4];
                rem[0] &= ~row[0]; rem[1] &= ~row[1];
                rem[2] &= ~row[2]; rem[3] &= ~row[3];
            }
        }
        int nkeep = __popc(kw[0]) + __popc(kw[1]) + __popc(kw[2]) + __popc(kw[3]);
        base = atomicAdd(&g_poolCnt[b], nkeep);
        kw0 = kw[0]; kw1 = kw[1]; kw2 = kw[2]; kw3 = kw[3];
    }
    kw0 = __shfl_sync(0xffffffffu, kw0, 0);
    kw1 = __shfl_sync(0xffffffffu, kw1, 0);
    kw2 = __shfl_sync(0xffffffffu, kw2, 0);
    kw3 = __shfl_sync(0xffffffffu, kw3, 0);
    base = __shfl_sync(0xffffffffu, base, 0);

    int pre1 = __popc(kw0);
    int pre2 = pre1 + __popc(kw1);
    int pre3 = pre2 + __popc(kw2);
#pragma unroll
    for (int r = 0; r < 4; r++) {
        int e = r * 32 + lane;
        u32 kwr = (r == 0) ? kw0 : (r == 1) ? kw1 : (r == 2) ? kw2 : kw3;
        int prer = (r == 0) ? 0 : (r == 1) ? pre1 : (r == 2) ? pre2 : pre3;
        if (e < K && ((kwr >> lane) & 1u)) {
            int rank = prer + __popc(kwr & ((1u << lane) - 1u));
            u64 kk = key[r];
            int a = (int)(~(u32)kk) & 0xFFF;
            int flat = c * KMAX + e;
            u64 det = (kk & 0xFFFFFFFF00000000ULL)
                    | ((u64)(u32)(32767 - flat) << 17)
                    | ((u64)(u32)a << 5);
            int pos = base + rank;
            if (pos < POOLCAP) g_pool[(size_t)b * POOLCAP + pos] = det;
        }
    }
}

// -------- kernel 3: big-class fallback + early-exit radix top-100 --------
__global__ void __launch_bounds__(1024) k_top(float* __restrict__ out) {
    __shared__ int hist[4096];
    __shared__ int segs[256];
    __shared__ u64 sel[128];
    __shared__ int sh_cnt;
    __shared__ u64 sh_prefix;
    __shared__ int sh_rem, sh_total;
    // fallback NMS scratch (only touched when g_bigCnt > 0)
    __shared__ u64 fkeys[CAP];
    __shared__ float4 fbox[KMAX];
    __shared__ float farea[KMAX];
    __shared__ u32 fmask[KMAX * WMAX];
    __shared__ int fkl[KMAX];
    __shared__ int f_nk, f_base;

    int b = blockIdx.x, tid = threadIdx.x;

    // ---- rare fallback: block-level NMS for this image's m>128 classes ----
    int nbig = g_bigCnt;
    for (int idx = 0; idx < nbig; idx++) {
        int li = g_bigList[idx];
        if (li / CM1 != b) continue;
        int c = li - b * CM1;
        int mm = g_candCnt[li];
        if (mm > CAP) mm = CAP;

        int n = 1; while (n < mm) n <<= 1;
        for (int i = tid; i < n; i += 1024)
            fkeys[i] = (i < mm) ? g_cand[(size_t)li * CAP + i] : 0ULL;
        __syncthreads();
        for (int k = 2; k <= n; k <<= 1)
            for (int j = k >> 1; j > 0; j >>= 1) {
                for (int i = tid; i < n; i += 1024) {
                    int x = i ^ j;
                    if (x > i) {
                        u64 A = fkeys[i], Bv = fkeys[x];
                        bool up = (i & k) == 0;
                        if (up ? (A < Bv) : (A > Bv)) { fkeys[i] = Bv; fkeys[x] = A; }
                    }
                }
                __syncthreads();
            }

        int K = mm < KMAX ? mm : KMAX;
        for (int r = tid; r < K; r += 1024) {
            int a = (int)(~(u32)fkeys[r]);
            float4 bb = g_boxes[b * NA + a];
            fbox[r] = bb;
            farea[r] = fmaxf(bb.z - bb.x, 0.f) * fmaxf(bb.w - bb.y, 0.f);
        }
        __syncthreads();

        int W = (K + 31) >> 5;
        for (int w = tid; w < K * W; w += 1024) {
            int i = w / W, seg = w - i * W;
            u32 bits = 0;
            float4 bi = fbox[i];
            float ai = farea[i];
            int j0 = seg << 5;
            int je = min(j0 + 32, K);
            for (int j = max(j0, i + 1); j < je; j++) {
                float4 bj = fbox[j];
                float iw = fminf(bi.z, bj.z) - fmaxf(bi.x, bj.x);
                float ih = fminf(bi.w, bj.w) - fmaxf(bi.y, bj.y);
                iw = fmaxf(iw, 0.f); ih = fmaxf(ih, 0.f);
                float inter = iw * ih;
                float uni = ai + farea[j] - inter;
                if (inter > 0.4985f * uni)
                    if (__fdiv_rn(inter, fmaxf(uni, 1e-9f)) > 0.5f)
                        bits |= 1u << (j - j0);
            }
            fmask[i * W + seg] = bits;
        }
        __syncthreads();

        if (tid == 0) {
            u32 remv[WMAX] = {0, 0, 0, 0, 0, 0, 0};
            int nkeep = 0;
            for (int i = 0; i < K; i++) {
                if (!((remv[i >> 5] >> (i & 31)) & 1u)) {
                    fkl[nkeep++] = i;
                    for (int w = 0; w < W; w++) remv[w] |= fmask[i * W + w];
                }
            }
            f_nk = nkeep;
            f_base = atomicAdd(&g_poolCnt[b], nkeep);
        }
        __syncthreads();

        int nk = f_nk, bse = f_base;
        for (int sidx = tid; sidx < nk; sidx += 1024) {
            int i = fkl[sidx];
            u64 kk = fkeys[i];
            int a = (int)(~(u32)kk) & 0xFFF;
            int flat = c * KMAX + i;
            u64 det = (kk & 0xFFFFFFFF00000000ULL)
                    | ((u64)(u32)(32767 - flat) << 17)
                    | ((u64)(u32)a << 5);
            int pos = bse + sidx;
            if (pos < POOLCAP) g_pool[(size_t)b * POOLCAP + pos] = det;
        }
        __syncthreads();
    }

    // ---- early-exit 12-bit radix select: stop once candidate set <= 128 ----
    int m = g_poolCnt[b]; if (m > POOLCAP) m = POOLCAP;
    const u64* pool = g_pool + (size_t)b * POOLCAP;

    u64 kth = 0;
    if (m > 100) {
        u64 prefix = 0; int rem = 100;
        for (int pass = 0; pass < 4; pass++) {
            int shift = 52 - 12 * pass;
            for (int d = tid; d < 4096; d += 1024) hist[d] = 0;
            __syncthreads();
            for (int i = tid; i < m; i += 1024) {
                u64 kk = pool[i];
                if (pass == 0 || (kk >> (shift + 12)) == prefix)
                    atomicAdd(&hist[(int)((kk >> shift) & 0xFFF)], 1);
            }
            __syncthreads();
            if (tid < 256) {
                int s = 0;
#pragma unroll
                for (int q = 0; q < 16; q++) s += hist[tid * 16 + q];
                segs[tid] = s;
            }
            __syncthreads();
            for (int off = 1; off < 256; off <<= 1) {
                int v = 0;
                if (tid < 256 && tid + off < 256) v = segs[tid + off];
                __syncthreads();
                if (tid < 256) segs[tid] += v;
                __syncthreads();
            }
            if (tid < 256) {
                int run = (tid < 255) ? segs[tid + 1] : 0;
#pragma unroll
                for (int q = 15; q >= 0; q--) {
                    int d = tid * 16 + q;
                    int ge = run + hist[d];
                    if (ge >= rem && run < rem) {
                        sh_prefix = (prefix << 12) | (u64)d;
                        sh_rem = rem - run;
                        sh_total = (100 - rem) + ge;   // #keys >= candidate threshold
                    }
                    run = ge;
                }
            }
            __syncthreads();
            prefix = sh_prefix; rem = sh_rem;
            int total = sh_total;
            __syncthreads();
            kth = prefix << shift;
            if (total <= 128) break;      // selection set fits; threshold is sufficient
        }
    }

    if (tid == 0) sh_cnt = 0;
    __syncthreads();
    for (int i = tid; i < m; i += 1024) {
        u64 kk = pool[i];
        if (kk >= kth) {
            int p = atomicAdd(&sh_cnt, 1);
            if (p < 128) sel[p] = kk;
        }
    }
    __syncthreads();
    int cnt = sh_cnt; if (cnt > 128) cnt = 128;
    int nsel = cnt < 100 ? cnt : 100;
    if (tid < 128 && tid >= cnt) sel[tid] = 0;
    __syncthreads();

    for (int k = 2; k <= 128; k <<= 1)
        for (int j = k >> 1; j > 0; j >>= 1) {
            if (tid < 128) {
                int i = tid, x = i ^ j;
                if (x > i) {
                    u64 A = sel[i], Bv = sel[x];
                    bool up = (i & k) == 0;
                    if (up ? (A < Bv) : (A > Bv)) { sel[i] = Bv; sel[x] = A; }
                }
            }
            __syncthreads();
        }

    for (int r = tid; r < 100; r += 1024) {
        float o0 = 0, o1 = 0, o2 = 0, o3 = 0, o4 = 0, o5 = 0;
        if (r < nsel) {
            u64 kk = sel[r];
            float sc = __uint_as_float((u32)(kk >> 32));
            int flat = 32767 - (int)((kk >> 17) & 0x7FFF);
            int cls = flat / 200 + 1;
            int a = (int)((kk >> 5) & 0xFFF);
            float4 bb = g_boxes[b * NA + a];
            o0 = bb.x; o1 = bb.y; o2 = bb.z; o3 = bb.w; o4 = sc; o5 = (float)cls;
        }
        float* op = out + ((size_t)b * 100 + r) * 6;
        op[0] = o0; op[1] = o1; op[2] = o2; op[3] = o3; op[4] = o4; op[5] = o5;
    }
}

// -------- launch --------
extern "C" void kernel_launch(void* const* d_in, const int* in_sizes, int n_in,
                              void* d_out, int out_size) {
    const float* logits = nullptr;
    const float* boxreg = nullptr;
    const float* priors = nullptr;
    for (int i = 0; i < n_in; i++) {
        if (in_sizes[i] == BATCH * NA * NC) logits = (const float*)d_in[i];
        else if (in_sizes[i] == BATCH * NA * 4) boxreg = (const float*)d_in[i];
        else if (in_sizes[i] == NA * 4) priors = (const float*)d_in[i];
    }
    float* out = (float*)d_out;

    k_decode<<<(BATCH * NA + 255) / 256, 256>>>(boxreg, priors);
    k_cand<<<(BATCH * NA + 7) / 8, 256>>>(logits);
    k_nms_warp<<<(BATCH * CM1 + 3) / 4, 128>>>();
    k_top<<<BATCH, 1024>>>(out);
}